// round 2
// baseline (speedup 1.0000x reference)
#include <cuda_runtime.h>
#include <cstdint>

// Problem constants (fixed by setup_inputs)
#define N      2048
#define DMDIM  128
#define KDIAG  (2*N - 1)           // 4095 anti-diagonals
#define DIAG_ELEMS (KDIAG * N)     // 8,386,560
#define BIGF   1e10f
#define GAMMA_ 0.1f
#define INVG   10.0f               // 1/GAMMA
#define MARGINF 2.0f

// Static scratch only (no runtime allocation allowed)
__device__ float  g_D[3][DIAG_ELEMS];   // diag-major: D[z][(i+j)*N + i]
__device__ float  g_norms[2][N];        // row squared-norms of x (0) and y (1)
__device__ float  g_dtw[3];             // softdtw(xy), softdtw(xx), softdtw(yy)
__device__ double g_part[512];          // fused idm block partials (2 x 256 blocks)

// ---------------------------------------------------------------------------
// Kernel 0: row squared norms for x and y
// ---------------------------------------------------------------------------
__global__ void norm_kernel(const float* __restrict__ x,
                            const float* __restrict__ y) {
    int r = blockIdx.x * blockDim.x + threadIdx.x;   // 0..2N-1
    if (r >= 2 * N) return;
    const float* p = (r < N) ? (x + (size_t)r * DMDIM)
                             : (y + (size_t)(r - N) * DMDIM);
    const float4* p4 = (const float4*)p;
    float s = 0.0f;
#pragma unroll
    for (int k = 0; k < DMDIM / 4; k++) {
        float4 v = p4[k];
        s += v.x * v.x + v.y * v.y + v.z * v.z + v.w * v.w;
    }
    g_norms[r < N ? 0 : 1][r < N ? r : r - N] = s;
}

// ---------------------------------------------------------------------------
// Kernel 1: pairwise sqdist -> diagonal-major layout, with fused contrastive
// IDM reduction for z=1 (x,x / a_idx) and z=2 (y,y / b_idx).
// 128x128 tile per 256-thread block, 8x8 micro-tile, k-chunks of 16.
// ---------------------------------------------------------------------------
#define TILE 128
#define KC   16

__global__ __launch_bounds__(256)
void pairdist_kernel(const float* __restrict__ x,
                     const float* __restrict__ y,
                     const float* __restrict__ aidx,
                     const float* __restrict__ bidx,
                     float thr) {
    int z = blockIdx.z;
    const float* A  = (z == 2) ? y : x;
    const float* B  = (z == 1) ? x : y;
    const float* nA = (z == 2) ? g_norms[1] : g_norms[0];
    const float* nB = (z == 1) ? g_norms[0] : g_norms[1];
    const float* gidx = (z == 1) ? aidx : bidx;   // only used when z != 0

    int bi = blockIdx.y, bj = blockIdx.x;
    __shared__ float As[TILE][KC + 1];
    __shared__ float Bs[TILE][KC + 1];

    int t  = threadIdx.x;
    int tx = t & 15, ty = t >> 4;

    float acc[8][8];
#pragma unroll
    for (int u = 0; u < 8; u++)
#pragma unroll
        for (int v = 0; v < 8; v++) acc[u][v] = 0.0f;

    for (int kb = 0; kb < DMDIM; kb += KC) {
        for (int idx = t; idx < TILE * KC; idx += 256) {
            int rr = idx >> 4, kk = idx & 15;
            As[rr][kk] = A[(size_t)(bi * TILE + rr) * DMDIM + kb + kk];
            Bs[rr][kk] = B[(size_t)(bj * TILE + rr) * DMDIM + kb + kk];
        }
        __syncthreads();
#pragma unroll
        for (int kk = 0; kk < KC; kk++) {
            float a[8], b[8];
#pragma unroll
            for (int u = 0; u < 8; u++) a[u] = As[ty + 16 * u][kk];
#pragma unroll
            for (int v = 0; v < 8; v++) b[v] = Bs[tx + 16 * v][kk];
#pragma unroll
            for (int u = 0; u < 8; u++)
#pragma unroll
                for (int v = 0; v < 8; v++) acc[u][v] += a[u] * b[v];
        }
        __syncthreads();
    }

    float* Dz = g_D[z];
    float idm_acc = 0.0f;
#pragma unroll
    for (int u = 0; u < 8; u++) {
        int gi = bi * TILE + ty + 16 * u;
        float na = nA[gi];
#pragma unroll
        for (int v = 0; v < 8; v++) {
            int gj = bj * TILE + tx + 16 * v;
            float d = fmaxf(na + nB[gj] - 2.0f * acc[u][v], 0.0f);
            Dz[(gi + gj) * N + gi] = d;
            if (z != 0) {
                float gd   = gidx[gi] - gidx[gj];
                float prob = fmaxf(MARGINF - d, 0.0f);
                idm_acc += ((fabsf(gd) - thr) > 0.0f)
                             ? (1.0f + gd * gd) * prob : d;
            }
        }
    }

    if (z != 0) {
        __shared__ double sh[256];
        sh[t] = (double)idm_acc;
        __syncthreads();
        for (int off = 128; off > 0; off >>= 1) {
            if (t < off) sh[t] += sh[t + off];
            __syncthreads();
        }
        if (t == 0)
            g_part[(z - 1) * 256 + bi * 16 + bj] = sh[0];
    }
}

// ---------------------------------------------------------------------------
// softmin cell:  out = d + softmin(left, up, diag)   (BIG-exact skip path)
// ---------------------------------------------------------------------------
__device__ __forceinline__ float cellf(float d, float left, float up,
                                       float dg, bool valid) {
    float lo = fminf(dg, up), hi = fmaxf(dg, up);
    float mm = fminf(lo, left);
    float o1 = fmaxf(lo, left);
    float o2 = hi;
    float m1 = mm - o1, m2 = mm - o2;        // both <= 0
    float smin;
    // If both margins <= -2.0, e1+e2 <= 2*exp(-20) < 2^-24, so
    // 1.0f + e1 + e2 == 1.0f bit-exactly and smin == mm exactly.
    if (fmaxf(m1, m2) > -2.0f) {
        float e1 = __expf(m1 * INVG);
        float e2 = __expf(m2 * INVG);
        smin = mm - GAMMA_ * __logf(1.0f + e1 + e2);
    } else {
        smin = mm;
    }
    return valid ? (d + smin) : BIGF;
}

// ---------------------------------------------------------------------------
// Kernel 2: soft-DTW anti-diagonal wavefront. One CTA per matrix.
// Register-resident r1/r2 per thread (columns t and t+1024), shfl neighbor
// exchange, double-buffered warp-boundary smem, depth-4 D-row prefetch.
// ---------------------------------------------------------------------------
__global__ __launch_bounds__(1024)
void softdtw_kernel() {
    __shared__ float4 bnd[2][32];     // per-warp lane31 {r1a,r2a,r1b,r2b}
    int m = blockIdx.x;
    const float* base = g_D[m];
    int t    = threadIdx.x;
    int lane = t & 31;
    int warp = t >> 5;

    // step-0 state: r1 = BIG except r1[0] = D[0,0]; r2 = BIG
    float r1a = (t == 0) ? base[0] : BIGF;
    float r2a = BIGF;
    float r1b = BIGF;
    float r2b = BIGF;
    if (t < 64) bnd[t >> 5][t & 31] = make_float4(BIGF, BIGF, BIGF, BIGF);

    // prefetch pipeline: rows k=1..4 in slots 0..3
    float pa[4], pb[4];
#pragma unroll
    for (int q = 0; q < 4; q++) {
        pa[q] = base[(1 + q) * N + t];
        pb[q] = base[(1 + q) * N + t + 1024];
    }
    __syncthreads();

#pragma unroll 4
    for (int k = 1; k < KDIAG; k++) {
        int s = (k - 1) & 3;
        float dA = pa[s];
        float dB = pb[s];
        int nk = k + 4;
        if (nk < KDIAG) {                 // refill slot for row k+4
            pa[s] = base[nk * N + t];
            pb[s] = base[nk * N + t + 1024];
        }

        // neighbor (i-1) values of r1/r2 via shfl; warp boundary via smem
        float p1a = __shfl_up_sync(0xffffffffu, r1a, 1);
        float p2a = __shfl_up_sync(0xffffffffu, r2a, 1);
        float p1b = __shfl_up_sync(0xffffffffu, r1b, 1);
        float p2b = __shfl_up_sync(0xffffffffu, r2b, 1);
        if (lane == 0) {
            int rb = (k & 1) ^ 1;         // buffer written at step k-1
            if (warp > 0) {
                float4 v = bnd[rb][warp - 1];
                p1a = v.x; p2a = v.y; p1b = v.z; p2b = v.w;
            } else {
                float4 v = bnd[rb][31];   // element 1023 feeds element 1024
                p1a = BIGF; p2a = BIGF;   // element 0 has no i-1
                p1b = v.x;  p2b = v.y;
            }
        }

        bool va = (t <= k)            && (k - t < N);
        bool vb = (t + 1024 <= k)     && (k - (t + 1024) < N);
        float oa = cellf(dA, r1a, p1a, p2a, va);
        float ob = cellf(dB, r1b, p1b, p2b, vb);
        r2a = r1a; r1a = oa;
        r2b = r1b; r1b = ob;

        if (lane == 31)
            bnd[k & 1][warp] = make_float4(r1a, r2a, r1b, r2b);
        __syncthreads();
    }
    if (t == 1023) g_dtw[m] = r1b;    // element i=2047 after step k=4094
}

// ---------------------------------------------------------------------------
// Kernel 3: combine -> scalar output
// ---------------------------------------------------------------------------
__global__ __launch_bounds__(256)
void combine_kernel(float* __restrict__ out) {
    __shared__ double sh[256];
    double s = 0.0;
    for (int i = threadIdx.x; i < 512; i += 256) s += g_part[i];
    sh[threadIdx.x] = s;
    __syncthreads();
    for (int off = 128; off > 0; off >>= 1) {
        if (threadIdx.x < off) sh[threadIdx.x] += sh[threadIdx.x + off];
        __syncthreads();
    }
    if (threadIdx.x == 0) {
        double pos = (double)g_dtw[0] - 0.5 * ((double)g_dtw[1] + (double)g_dtw[2]);
        out[0] = (float)((pos + sh[0]) * (1.0 / 2048.0));   // / NUM_FRAMES
    }
}

// ---------------------------------------------------------------------------
extern "C" void kernel_launch(void* const* d_in, const int* in_sizes, int n_in,
                              void* d_out, int out_size) {
    const float* a_emb = (const float*)d_in[0];
    const float* b_emb = (const float*)d_in[1];
    const float* a_idx = (const float*)d_in[2];
    const float* b_idx = (const float*)d_in[3];
    int n = in_sizes[2];                       // 2048
    float thr = 10.0f / (float)n;              // SIGMA / seq_len (exact dyadic)

    norm_kernel<<<(2 * N + 255) / 256, 256>>>(a_emb, b_emb);

    dim3 pg(N / TILE, N / TILE, 3);
    pairdist_kernel<<<pg, 256>>>(a_emb, b_emb, a_idx, b_idx, thr);

    softdtw_kernel<<<3, 1024>>>();

    combine_kernel<<<1, 256>>>((float*)d_out);
}